// round 10
// baseline (speedup 1.0000x reference)
#include <cuda_runtime.h>
#include <cuda_bf16.h>
#include <cstdint>

// Problem constants (shapes fixed by the dataset)
static constexpr int NMAX = 50000;
static constexpr int EMAX = 800000;
static constexpr int SCAN_BLK = 1024;

// Scratch (static device allocations — no cudaMalloc allowed).
__device__ __align__(16) float g_deg[NMAX];
__device__ __align__(16) float g_dinv[NMAX];
__device__ __align__(16) float g_sn[NMAX];                 // dinv^2 (self-loop norm)
__device__ __align__(16) float g_H1[(size_t)NMAX * 256];   // x @ W1
__device__ __align__(16) float g_AG1[(size_t)NMAX * 256];  // aggregated layer1
__device__ __align__(16) float g_H2[(size_t)NMAX * 128];   // relu(AG1+b1) @ W2
__device__ __align__(16) float g_AG2[(size_t)NMAX * 128];  // aggregated layer2
__device__ __align__(16) int   g_cnt[NMAX];                // in-degree histogram
__device__ __align__(16) int   g_rowptr[NMAX + 1];         // CSR offsets (by dst)
__device__ __align__(16) int   g_fill[NMAX];               // scatter cursors
__device__ __align__(16) int   g_src[EMAX];                // CSR: source node per edge
__device__ __align__(16) float g_wgt[EMAX];                // CSR: norm per edge
__device__ __align__(16) int   g_part[64];                 // scan block partials

// ---------------------------------------------------------------------------
// mma.sync + cp.async helpers (base PTX ISA, sm_80+ — safe on plain sm_103)
// ---------------------------------------------------------------------------
__device__ __forceinline__ void ldsm4(uint32_t* r, uint32_t addr) {
    asm volatile(
        "ldmatrix.sync.aligned.m8n8.x4.shared.b16 {%0,%1,%2,%3}, [%4];"
        : "=r"(r[0]), "=r"(r[1]), "=r"(r[2]), "=r"(r[3]) : "r"(addr));
}
__device__ __forceinline__ void mma_bf16(float* c, const uint32_t* a,
                                         const uint32_t* b) {
    asm volatile(
        "mma.sync.aligned.m16n8k16.row.col.f32.bf16.bf16.f32 "
        "{%0,%1,%2,%3}, {%4,%5,%6,%7}, {%8,%9}, {%0,%1,%2,%3};"
        : "+f"(c[0]), "+f"(c[1]), "+f"(c[2]), "+f"(c[3])
        : "r"(a[0]), "r"(a[1]), "r"(a[2]), "r"(a[3]), "r"(b[0]), "r"(b[1]));
}
__device__ __forceinline__ void cp16(uint32_t dst, const void* src, bool valid) {
    int sz = valid ? 16 : 0;
    asm volatile("cp.async.cg.shared.global [%0], [%1], 16, %2;"
                 :: "r"(dst), "l"(src), "r"(sz));
}
__device__ __forceinline__ void cp_commit() {
    asm volatile("cp.async.commit_group;");
}
__device__ __forceinline__ void cp_wait0() {
    asm volatile("cp.async.wait_group 0;");
}
// bf16 hi/lo split (Markidis): v = hi + lo + O(2^-17 |v|)
__device__ __forceinline__ void split2(float v, __nv_bfloat16& h,
                                       __nv_bfloat16& l) {
    h = __float2bfloat16(v);
    l = __float2bfloat16(v - __bfloat162float(h));
}

// ---------------------------------------------------------------------------
// Degree / histogram preparation (edge_index is int32: JAX x64 disabled)
// ---------------------------------------------------------------------------
__global__ void deg_init_kernel(float* __restrict__ deg, int* __restrict__ cnt,
                                int n) {
    int i = blockIdx.x * blockDim.x + threadIdx.x;
    if (i < n) { deg[i] = 1.0f; cnt[i] = 0; }
}

__global__ void deg_accum_kernel(const int* __restrict__ ei,
                                 const float* __restrict__ w,
                                 float* __restrict__ deg, int* __restrict__ cnt,
                                 int E, int n) {
    int e = blockIdx.x * blockDim.x + threadIdx.x;
    if (e < E) {
        int c = ei[E + e];
        if ((unsigned)c < (unsigned)n) {
            atomicAdd(&deg[c], w[e]);
            atomicAdd(&cnt[c], 1);
        }
    }
}

__global__ void dinv_kernel(const float* __restrict__ deg,
                            float* __restrict__ dinv,
                            float* __restrict__ sn, int n) {
    int i = blockIdx.x * blockDim.x + threadIdx.x;
    if (i < n) {
        float d = deg[i];
        float v = d > 0.f ? rsqrtf(d) : 0.f;
        dinv[i] = v;
        sn[i] = v * v;
    }
}

// ---- Multi-block exclusive scan ----
__global__ __launch_bounds__(256)
void scan_reduce_kernel(const int* __restrict__ cnt, int* __restrict__ part,
                        int n) {
    __shared__ int sh[256];
    int base = blockIdx.x * SCAN_BLK;
    int t = threadIdx.x;
    int s = 0;
#pragma unroll
    for (int j = 0; j < 4; ++j) {
        int i = base + t + j * 256;
        if (i < n) s += cnt[i];
    }
    sh[t] = s;
    __syncthreads();
    for (int o = 128; o > 0; o >>= 1) {
        if (t < o) sh[t] += sh[t + o];
        __syncthreads();
    }
    if (t == 0) part[blockIdx.x] = sh[0];
}

__global__ __launch_bounds__(64)
void scan_partials_kernel(int* __restrict__ part, int nblk) {
    __shared__ int ws[2];
    int t = threadIdx.x, lane = t & 31, wid = t >> 5;
    int v = (t < nblk) ? part[t] : 0;
    int s = v;
#pragma unroll
    for (int o = 1; o < 32; o <<= 1) {
        int u = __shfl_up_sync(0xffffffffu, s, o);
        if (lane >= o) s += u;
    }
    if (lane == 31) ws[wid] = s;
    __syncthreads();
    int excl = s - v + (wid ? ws[0] : 0);
    if (t < nblk) part[t] = excl;
}

__global__ __launch_bounds__(1024)
void scan_final_kernel(const int* __restrict__ cnt, const int* __restrict__ part,
                       int* __restrict__ rowptr, int* __restrict__ fill, int n) {
    __shared__ int wsum[32];
    __shared__ int wpre[32];
    int t = threadIdx.x, lane = t & 31, wid = t >> 5;
    int i = blockIdx.x * SCAN_BLK + t;
    int v = (i < n) ? cnt[i] : 0;
    int s = v;
#pragma unroll
    for (int o = 1; o < 32; o <<= 1) {
        int u = __shfl_up_sync(0xffffffffu, s, o);
        if (lane >= o) s += u;
    }
    if (lane == 31) wsum[wid] = s;
    __syncthreads();
    if (wid == 0) {
        int ws = wsum[lane];
#pragma unroll
        for (int o = 1; o < 32; o <<= 1) {
            int u = __shfl_up_sync(0xffffffffu, ws, o);
            if (lane >= o) ws += u;
        }
        wpre[lane] = ws;
    }
    __syncthreads();
    int excl = part[blockIdx.x] + (wid ? wpre[wid - 1] : 0) + s - v;
    if (i < n) {
        rowptr[i] = excl;
        fill[i] = excl;
        if (i == n - 1) rowptr[n] = excl + v;
    }
}

__global__ void scatter_kernel(const int* __restrict__ ei,
                               const float* __restrict__ w,
                               const float* __restrict__ dinv,
                               int* __restrict__ fill,
                               int* __restrict__ src, float* __restrict__ wgt,
                               int E, int n) {
    int e = blockIdx.x * blockDim.x + threadIdx.x;
    if (e < E) {
        int c = ei[E + e];
        if ((unsigned)c < (unsigned)n) {
            int r = ei[e];
            bool rok = (unsigned)r < (unsigned)n;
            float nm = rok ? dinv[r] * w[e] * dinv[c] : 0.f;
            int pos = atomicAdd(&fill[c], 1);
            src[pos] = rok ? r : 0;
            wgt[pos] = nm;
        }
    }
}

// ---------------------------------------------------------------------------
// bf16-split mma.sync GEMM, cp.async pipelined.
// C[M,Nc] = epiA(A[M,K]) @ W[K,Nc] (+ cbias)
// 128x128x32 CTA tile, 8 warps (2x4), warp tile 64x32, m16n8k16 HMMA.
// D += Ah*Bh + Ah*Bl + Al*Bh  (fp32 accum; ~4e-6 element error)
// Raw fp32 tiles staged via cp.async; convert+split smem->smem; next tile's
// copies overlap with the current tile's MMAs.
// ---------------------------------------------------------------------------
// Dynamic smem layout (bytes):
static constexpr int OFF_AH   = 0;                 // bf16 [128][40]
static constexpr int OFF_AL   = 10240;
static constexpr int OFF_BH   = 20480;
static constexpr int OFF_BL   = 30720;
static constexpr int OFF_ARAW = 40960;             // fp32 [128][36]
static constexpr int OFF_BRAW = 59392;             // fp32 [32][132]
static constexpr int SMEM_MMA = 59392 + 16896;     // 76288 B

template <bool A_BIAS, bool A_RELU, bool C_BIAS>
__global__ __launch_bounds__(256, 2)
void gemm_mma_kernel(const float* __restrict__ A, const float* __restrict__ W,
                     const float* __restrict__ ab, const float* __restrict__ cb,
                     float* __restrict__ C, int M, int K, int Nc) {
    extern __shared__ __align__(16) char smem[];
    __nv_bfloat16* Ah = (__nv_bfloat16*)(smem + OFF_AH);   // [r*40 + k]
    __nv_bfloat16* Al = (__nv_bfloat16*)(smem + OFF_AL);
    __nv_bfloat16* Bh = (__nv_bfloat16*)(smem + OFF_BH);   // [n*40 + k]
    __nv_bfloat16* Bl = (__nv_bfloat16*)(smem + OFF_BL);
    float* Araw = (float*)(smem + OFF_ARAW);               // [r*36 + c]
    float* Braw = (float*)(smem + OFF_BRAW);               // [k*132 + n]
    const uint32_t sbase = (uint32_t)__cvta_generic_to_shared(smem);

    const int tid = threadIdx.x;
    const int lane = tid & 31;
    const int wid = tid >> 5;
    const int wr = wid >> 2;        // 0..1 (warp row)
    const int wc = wid & 3;         // 0..3 (warp col)
    const int rowBase = blockIdx.y * 128;
    const int colBase = blockIdx.x * 128;

    const int lrow = lane & 7;
    const int lgrp = lane >> 3;     // 0..3 ldmatrix address group

    float acc[4][4][4];
#pragma unroll
    for (int i = 0; i < 4; ++i)
#pragma unroll
        for (int j = 0; j < 4; ++j)
#pragma unroll
            for (int k = 0; k < 4; ++k) acc[i][j][k] = 0.f;

    // issue cp.async copies for one 32-wide K chunk
    auto issue_loads = [&](int k0) {
#pragma unroll
        for (int j = 0; j < 4; ++j) {          // A: 128 rows x 32 cols fp32
            int lin = tid + j * 256;           // 1024 float4 chunks
            int r = lin >> 3;
            int q = lin & 7;
            int grow = rowBase + r;
            bool ok = grow < M;
            const float* src = A + (size_t)(ok ? grow : 0) * K + k0 + q * 4;
            cp16(sbase + OFF_ARAW + (uint32_t)(r * 36 + q * 4) * 4, src, ok);
        }
#pragma unroll
        for (int j = 0; j < 4; ++j) {          // B: 32 rows x 128 cols fp32
            int lin = tid + j * 256;
            int kr = lin >> 5;
            int q = lin & 31;
            const float* src = W + (size_t)(k0 + kr) * Nc + colBase + q * 4;
            cp16(sbase + OFF_BRAW + (uint32_t)(kr * 132 + q * 4) * 4, src, true);
        }
        cp_commit();
    };

    issue_loads(0);
    const int nChunks = K >> 5;
    for (int c = 0; c < nChunks; ++c) {
        const int k0 = c << 5;
        cp_wait0();
        __syncthreads();   // raw tiles visible to all; prev MMA phase done

        // ---- convert: raw fp32 -> hi/lo bf16 (smem -> smem) ----
#pragma unroll
        for (int j = 0; j < 4; ++j) {
            int lin = tid + j * 256;
            int r = lin >> 3;
            int q = lin & 7;
            float4 v = *(const float4*)&Araw[r * 36 + q * 4];
            if (A_BIAS) {
                float4 bb = *(const float4*)(ab + k0 + q * 4);
                v.x += bb.x; v.y += bb.y; v.z += bb.z; v.w += bb.w;
            }
            if (A_RELU) {
                v.x = fmaxf(v.x, 0.f); v.y = fmaxf(v.y, 0.f);
                v.z = fmaxf(v.z, 0.f); v.w = fmaxf(v.w, 0.f);
            }
            __nv_bfloat16 h[4], l[4];
            split2(v.x, h[0], l[0]); split2(v.y, h[1], l[1]);
            split2(v.z, h[2], l[2]); split2(v.w, h[3], l[3]);
            *(uint2*)&Ah[r * 40 + q * 4] = *(const uint2*)h;
            *(uint2*)&Al[r * 40 + q * 4] = *(const uint2*)l;
        }
        {
            int n = tid & 127;
            int kh = tid >> 7;              // 0..1
#pragma unroll
            for (int kk = 0; kk < 16; ++kk) {
                int k = kh * 16 + kk;
                float v = Braw[k * 132 + n];
                __nv_bfloat16 h, l;
                split2(v, h, l);
                Bh[n * 40 + k] = h;
                Bl[n * 40 + k] = l;
            }
        }
        __syncthreads();

        // overlap: next chunk's copies fly during this chunk's MMAs
        if (c + 1 < nChunks) issue_loads(k0 + 32);

#pragma unroll
        for (int ks = 0; ks < 32; ks += 16) {
            uint32_t aH[4][4], aL[4][4], bH[4][2], bL[4][2];
#pragma unroll
            for (int mf = 0; mf < 4; ++mf) {
                int r = wr * 64 + mf * 16 + lrow + ((lgrp & 1) ? 8 : 0);
                int cc = ks + ((lgrp & 2) ? 8 : 0);
                uint32_t off = (uint32_t)(r * 40 + cc) * 2;
                ldsm4(aH[mf], sbase + OFF_AH + off);
                ldsm4(aL[mf], sbase + OFF_AL + off);
            }
#pragma unroll
            for (int nf2 = 0; nf2 < 2; ++nf2) {
                int r = wc * 32 + nf2 * 16 + lrow + ((lgrp >> 1) ? 8 : 0);
                int cc = ks + ((lgrp & 1) ? 8 : 0);
                uint32_t off = (uint32_t)(r * 40 + cc) * 2;
                uint32_t t[4];
                ldsm4(t, sbase + OFF_BH + off);
                bH[nf2 * 2][0] = t[0]; bH[nf2 * 2][1] = t[1];
                bH[nf2 * 2 + 1][0] = t[2]; bH[nf2 * 2 + 1][1] = t[3];
                ldsm4(t, sbase + OFF_BL + off);
                bL[nf2 * 2][0] = t[0]; bL[nf2 * 2][1] = t[1];
                bL[nf2 * 2 + 1][0] = t[2]; bL[nf2 * 2 + 1][1] = t[3];
            }
#pragma unroll
            for (int mf = 0; mf < 4; ++mf)
#pragma unroll
                for (int nf = 0; nf < 4; ++nf) {
                    mma_bf16(acc[mf][nf], aH[mf], bH[nf]);
                    mma_bf16(acc[mf][nf], aH[mf], bL[nf]);
                    mma_bf16(acc[mf][nf], aL[mf], bH[nf]);
                }
        }
    }

    // ---- epilogue ----
#pragma unroll
    for (int mf = 0; mf < 4; ++mf) {
        int row = rowBase + wr * 64 + mf * 16 + (lane >> 2);
#pragma unroll
        for (int nf = 0; nf < 4; ++nf) {
            int col = colBase + wc * 32 + nf * 8 + (lane & 3) * 2;
            float b0 = 0.f, b1 = 0.f;
            if (C_BIAS) { b0 = cb[col]; b1 = cb[col + 1]; }
            if (row < M)
                *(float2*)(C + (size_t)row * Nc + col) =
                    make_float2(acc[mf][nf][0] + b0, acc[mf][nf][1] + b1);
            if (row + 8 < M)
                *(float2*)(C + (size_t)(row + 8) * Nc + col) =
                    make_float2(acc[mf][nf][2] + b0, acc[mf][nf][3] + b1);
        }
    }
}

// ---------------------------------------------------------------------------
// CSR aggregation: one warp per destination node (no atomics).
// ---------------------------------------------------------------------------
template <int D>
__global__ __launch_bounds__(256)
void agg_csr_kernel(const float* __restrict__ H,
                    const int* __restrict__ rowptr,
                    const int* __restrict__ src,
                    const float* __restrict__ wgt,
                    const float* __restrict__ sn,
                    float* __restrict__ AG, int n) {
    constexpr int V = D / 128;
    int node = (blockIdx.x * 256 + threadIdx.x) >> 5;
    int lane = threadIdx.x & 31;
    if (node >= n) return;

    float s = __ldg(&sn[node]);
    const float4* hself = (const float4*)(H + (size_t)node * D);
    float4 acc[V];
#pragma unroll
    for (int v = 0; v < V; ++v) {
        float4 h = __ldg(&hself[lane + 32 * v]);
        acc[v] = make_float4(h.x * s, h.y * s, h.z * s, h.w * s);
    }

    int e0 = __ldg(&rowptr[node]);
    int e1 = __ldg(&rowptr[node + 1]);
    for (int e = e0; e < e1; ++e) {
        int r = __ldg(&src[e]);
        float nm = __ldg(&wgt[e]);
        const float4* hs = (const float4*)(H + (size_t)r * D);
#pragma unroll
        for (int v = 0; v < V; ++v) {
            float4 h = __ldg(&hs[lane + 32 * v]);
            acc[v].x += nm * h.x;
            acc[v].y += nm * h.y;
            acc[v].z += nm * h.z;
            acc[v].w += nm * h.w;
        }
    }

    float4* dst = (float4*)(AG + (size_t)node * D);
#pragma unroll
    for (int v = 0; v < V; ++v) dst[lane + 32 * v] = acc[v];
}

// ---------------------------------------------------------------------------
// Launcher. gemm1 stays at launch index 3 (profiled slot).
// ---------------------------------------------------------------------------
extern "C" void kernel_launch(void* const* d_in, const int* in_sizes, int n_in,
                              void* d_out, int out_size) {
    const float* x  = (const float*)d_in[0];
    const int*   ei = (const int*)d_in[1];     // int32 (JAX x64 disabled)
    const float* ew = (const float*)d_in[2];
    const float* W1 = (const float*)d_in[3];
    const float* b1 = (const float*)d_in[4];
    const float* W2 = (const float*)d_in[5];
    const float* b2 = (const float*)d_in[6];
    const float* Wp = (const float*)d_in[7];
    const float* bp = (const float*)d_in[8];
    float* out = (float*)d_out;

    const int M = in_sizes[0] / 512;   // 50000
    const int E = in_sizes[2];         // 800000

    float *deg, *dinv, *sn, *H1, *AG1, *H2, *AG2, *wgt;
    int *cnt, *rowptr, *fill, *src, *part;
    cudaGetSymbolAddress((void**)&deg,    g_deg);
    cudaGetSymbolAddress((void**)&dinv,   g_dinv);
    cudaGetSymbolAddress((void**)&sn,     g_sn);
    cudaGetSymbolAddress((void**)&H1,     g_H1);
    cudaGetSymbolAddress((void**)&AG1,    g_AG1);
    cudaGetSymbolAddress((void**)&H2,     g_H2);
    cudaGetSymbolAddress((void**)&AG2,    g_AG2);
    cudaGetSymbolAddress((void**)&cnt,    g_cnt);
    cudaGetSymbolAddress((void**)&rowptr, g_rowptr);
    cudaGetSymbolAddress((void**)&fill,   g_fill);
    cudaGetSymbolAddress((void**)&src,    g_src);
    cudaGetSymbolAddress((void**)&wgt,    g_wgt);
    cudaGetSymbolAddress((void**)&part,   g_part);

    // raise dynamic smem limit (idempotent host calls; no allocation)
    cudaFuncSetAttribute(gemm_mma_kernel<false, false, false>,
                         cudaFuncAttributeMaxDynamicSharedMemorySize, SMEM_MMA);
    cudaFuncSetAttribute(gemm_mma_kernel<true, true, false>,
                         cudaFuncAttributeMaxDynamicSharedMemorySize, SMEM_MMA);
    cudaFuncSetAttribute(gemm_mma_kernel<true, false, true>,
                         cudaFuncAttributeMaxDynamicSharedMemorySize, SMEM_MMA);

    const int TB = 256;
    const int rowBlocks = (M + 127) / 128;     // 391
    const int aggBlocks = (M + 7) / 8;
    const int nblk = (M + SCAN_BLK - 1) / SCAN_BLK;

    // launches 0..2: degree prep
    deg_init_kernel<<<(M + TB - 1) / TB, TB>>>(deg, cnt, M);
    deg_accum_kernel<<<(E + TB - 1) / TB, TB>>>(ei, ew, deg, cnt, E, M);
    dinv_kernel<<<(M + TB - 1) / TB, TB>>>(deg, dinv, sn, M);

    // launch 3 (profiled): H1 = x @ W1  (bf16-split HMMA, cp.async pipelined)
    gemm_mma_kernel<false, false, false>
        <<<dim3(2, rowBlocks), 256, SMEM_MMA>>>(x, W1, nullptr, nullptr, H1,
                                                M, 512, 256);

    // CSR build (parallel scan) + scatter
    scan_reduce_kernel<<<nblk, 256>>>(cnt, part, M);
    scan_partials_kernel<<<1, 64>>>(part, nblk);
    scan_final_kernel<<<nblk, 1024>>>(cnt, part, rowptr, fill, M);
    scatter_kernel<<<(E + TB - 1) / TB, TB>>>(ei, ew, dinv, fill, src, wgt, E, M);

    // layer 1 aggregation
    agg_csr_kernel<256><<<aggBlocks, 256>>>(H1, rowptr, src, wgt, sn, AG1, M);

    // layer 2: H2 = relu(AG1 + b1) @ W2 ; AG2 = CSR-aggregate(H2)
    gemm_mma_kernel<true, true, false>
        <<<dim3(1, rowBlocks), 256, SMEM_MMA>>>(AG1, W2, b1, nullptr, H2,
                                                M, 256, 128);
    agg_csr_kernel<128><<<aggBlocks, 256>>>(H2, rowptr, src, wgt, sn, AG2, M);

    // projection: out = (AG2 + b2) @ Wp + bp
    gemm_mma_kernel<true, false, true>
        <<<dim3(1, rowBlocks), 256, SMEM_MMA>>>(AG2, Wp, b2, bp, out,
                                                M, 128, 128);
}

// round 11
// speedup vs baseline: 1.0781x; 1.0781x over previous
#include <cuda_runtime.h>
#include <cuda_bf16.h>
#include <cstdint>

// Problem constants (shapes fixed by the dataset)
static constexpr int NMAX = 50000;
static constexpr int EMAX = 800000;
static constexpr int SCAN_BLK = 1024;

// Scratch (static device allocations — no cudaMalloc allowed).
__device__ __align__(16) float g_deg[NMAX];
__device__ __align__(16) float g_dinv[NMAX];
__device__ __align__(16) float g_sn[NMAX];                 // dinv^2 (self-loop norm)
__device__ __align__(16) float g_H1[(size_t)NMAX * 256];   // x @ W1 (fp32)
__device__ __align__(16) float g_H2[(size_t)NMAX * 128];   // relu(AG1+b1) @ W2 (fp32)
__device__ __align__(16) int   g_cnt[NMAX];
__device__ __align__(16) int   g_rowptr[NMAX + 1];
__device__ __align__(16) int   g_fill[NMAX];
__device__ __align__(16) int   g_src[EMAX];
__device__ __align__(16) float g_wgt[EMAX];
__device__ __align__(16) int   g_part[64];
// bf16 hi/lo operands (pre-split; A-side row-major [m][k], W-side transposed [n][k])
__device__ __align__(16) __nv_bfloat16 g_Xh[(size_t)NMAX * 512];
__device__ __align__(16) __nv_bfloat16 g_Xl[(size_t)NMAX * 512];
__device__ __align__(16) __nv_bfloat16 g_A1h[(size_t)NMAX * 256];  // relu(AG1+b1)
__device__ __align__(16) __nv_bfloat16 g_A1l[(size_t)NMAX * 256];
__device__ __align__(16) __nv_bfloat16 g_A2h[(size_t)NMAX * 128];  // AG2+b2
__device__ __align__(16) __nv_bfloat16 g_A2l[(size_t)NMAX * 128];
__device__ __align__(16) __nv_bfloat16 g_W1h[256 * 512], g_W1l[256 * 512];
__device__ __align__(16) __nv_bfloat16 g_W2h[128 * 256], g_W2l[128 * 256];
__device__ __align__(16) __nv_bfloat16 g_Wph[128 * 128], g_Wpl[128 * 128];

// ---------------------------------------------------------------------------
// mma.sync + cp.async helpers (base PTX ISA, sm_80+ — safe on plain sm_103)
// ---------------------------------------------------------------------------
__device__ __forceinline__ void ldsm4(uint32_t* r, uint32_t addr) {
    asm volatile(
        "ldmatrix.sync.aligned.m8n8.x4.shared.b16 {%0,%1,%2,%3}, [%4];"
        : "=r"(r[0]), "=r"(r[1]), "=r"(r[2]), "=r"(r[3]) : "r"(addr));
}
__device__ __forceinline__ void mma_bf16(float* c, const uint32_t* a,
                                         const uint32_t* b) {
    asm volatile(
        "mma.sync.aligned.m16n8k16.row.col.f32.bf16.bf16.f32 "
        "{%0,%1,%2,%3}, {%4,%5,%6,%7}, {%8,%9}, {%0,%1,%2,%3};"
        : "+f"(c[0]), "+f"(c[1]), "+f"(c[2]), "+f"(c[3])
        : "r"(a[0]), "r"(a[1]), "r"(a[2]), "r"(a[3]), "r"(b[0]), "r"(b[1]));
}
__device__ __forceinline__ void cp16(uint32_t dst, const void* src, bool valid) {
    int sz = valid ? 16 : 0;
    asm volatile("cp.async.cg.shared.global [%0], [%1], 16, %2;"
                 :: "r"(dst), "l"(src), "r"(sz));
}
__device__ __forceinline__ void cp_commit() {
    asm volatile("cp.async.commit_group;");
}
__device__ __forceinline__ void cp_wait1() {
    asm volatile("cp.async.wait_group 1;");
}
__device__ __forceinline__ void cp_wait0() {
    asm volatile("cp.async.wait_group 0;");
}
// bf16 hi/lo split (Markidis): v = hi + lo + O(2^-17 |v|)
__device__ __forceinline__ void split2(float v, __nv_bfloat16& h,
                                       __nv_bfloat16& l) {
    h = __float2bfloat16(v);
    l = __float2bfloat16(v - __bfloat162float(h));
}

// ---------------------------------------------------------------------------
// Operand pre-split kernels
// ---------------------------------------------------------------------------
__global__ __launch_bounds__(256)
void split_x_kernel(const float* __restrict__ x, __nv_bfloat16* __restrict__ xh,
                    __nv_bfloat16* __restrict__ xl, size_t n4) {
    size_t i = (size_t)blockIdx.x * 256 + threadIdx.x;
    if (i >= n4) return;
    float4 v = ((const float4*)x)[i];
    __nv_bfloat16 h[4], l[4];
    split2(v.x, h[0], l[0]); split2(v.y, h[1], l[1]);
    split2(v.z, h[2], l[2]); split2(v.w, h[3], l[3]);
    ((uint2*)xh)[i] = *(const uint2*)h;
    ((uint2*)xl)[i] = *(const uint2*)l;
}

// W[K][Nc] -> Wt[n][k] hi/lo (tiny matrices; coalesced read, strided write)
__global__ __launch_bounds__(256)
void split_wT_kernel(const float* __restrict__ W, __nv_bfloat16* __restrict__ wh,
                     __nv_bfloat16* __restrict__ wl, int K, int Nc) {
    int idx = blockIdx.x * 256 + threadIdx.x;
    if (idx >= K * Nc) return;
    int k = idx / Nc, n = idx - k * Nc;
    __nv_bfloat16 h, l;
    split2(W[idx], h, l);
    wh[(size_t)n * K + k] = h;
    wl[(size_t)n * K + k] = l;
}

// ---------------------------------------------------------------------------
// Degree / histogram preparation (edge_index is int32: JAX x64 disabled)
// ---------------------------------------------------------------------------
__global__ void deg_init_kernel(float* __restrict__ deg, int* __restrict__ cnt,
                                int n) {
    int i = blockIdx.x * blockDim.x + threadIdx.x;
    if (i < n) { deg[i] = 1.0f; cnt[i] = 0; }
}

__global__ void deg_accum_kernel(const int* __restrict__ ei,
                                 const float* __restrict__ w,
                                 float* __restrict__ deg, int* __restrict__ cnt,
                                 int E, int n) {
    int e = blockIdx.x * blockDim.x + threadIdx.x;
    if (e < E) {
        int c = ei[E + e];
        if ((unsigned)c < (unsigned)n) {
            atomicAdd(&deg[c], w[e]);
            atomicAdd(&cnt[c], 1);
        }
    }
}

__global__ void dinv_kernel(const float* __restrict__ deg,
                            float* __restrict__ dinv,
                            float* __restrict__ sn, int n) {
    int i = blockIdx.x * blockDim.x + threadIdx.x;
    if (i < n) {
        float d = deg[i];
        float v = d > 0.f ? rsqrtf(d) : 0.f;
        dinv[i] = v;
        sn[i] = v * v;
    }
}

// ---- Multi-block exclusive scan ----
__global__ __launch_bounds__(256)
void scan_reduce_kernel(const int* __restrict__ cnt, int* __restrict__ part,
                        int n) {
    __shared__ int sh[256];
    int base = blockIdx.x * SCAN_BLK;
    int t = threadIdx.x;
    int s = 0;
#pragma unroll
    for (int j = 0; j < 4; ++j) {
        int i = base + t + j * 256;
        if (i < n) s += cnt[i];
    }
    sh[t] = s;
    __syncthreads();
    for (int o = 128; o > 0; o >>= 1) {
        if (t < o) sh[t] += sh[t + o];
        __syncthreads();
    }
    if (t == 0) part[blockIdx.x] = sh[0];
}

__global__ __launch_bounds__(64)
void scan_partials_kernel(int* __restrict__ part, int nblk) {
    __shared__ int ws[2];
    int t = threadIdx.x, lane = t & 31, wid = t >> 5;
    int v = (t < nblk) ? part[t] : 0;
    int s = v;
#pragma unroll
    for (int o = 1; o < 32; o <<= 1) {
        int u = __shfl_up_sync(0xffffffffu, s, o);
        if (lane >= o) s += u;
    }
    if (lane == 31) ws[wid] = s;
    __syncthreads();
    int excl = s - v + (wid ? ws[0] : 0);
    if (t < nblk) part[t] = excl;
}

__global__ __launch_bounds__(1024)
void scan_final_kernel(const int* __restrict__ cnt, const int* __restrict__ part,
                       int* __restrict__ rowptr, int* __restrict__ fill, int n) {
    __shared__ int wsum[32];
    __shared__ int wpre[32];
    int t = threadIdx.x, lane = t & 31, wid = t >> 5;
    int i = blockIdx.x * SCAN_BLK + t;
    int v = (i < n) ? cnt[i] : 0;
    int s = v;
#pragma unroll
    for (int o = 1; o < 32; o <<= 1) {
        int u = __shfl_up_sync(0xffffffffu, s, o);
        if (lane >= o) s += u;
    }
    if (lane == 31) wsum[wid] = s;
    __syncthreads();
    if (wid == 0) {
        int ws = wsum[lane];
#pragma unroll
        for (int o = 1; o < 32; o <<= 1) {
            int u = __shfl_up_sync(0xffffffffu, ws, o);
            if (lane >= o) ws += u;
        }
        wpre[lane] = ws;
    }
    __syncthreads();
    int excl = part[blockIdx.x] + (wid ? wpre[wid - 1] : 0) + s - v;
    if (i < n) {
        rowptr[i] = excl;
        fill[i] = excl;
        if (i == n - 1) rowptr[n] = excl + v;
    }
}

__global__ void scatter_kernel(const int* __restrict__ ei,
                               const float* __restrict__ w,
                               const float* __restrict__ dinv,
                               int* __restrict__ fill,
                               int* __restrict__ src, float* __restrict__ wgt,
                               int E, int n) {
    int e = blockIdx.x * blockDim.x + threadIdx.x;
    if (e < E) {
        int c = ei[E + e];
        if ((unsigned)c < (unsigned)n) {
            int r = ei[e];
            bool rok = (unsigned)r < (unsigned)n;
            float nm = rok ? dinv[r] * w[e] * dinv[c] : 0.f;
            int pos = atomicAdd(&fill[c], 1);
            src[pos] = rok ? r : 0;
            wgt[pos] = nm;
        }
    }
}

// ---------------------------------------------------------------------------
// Pure-bf16 pipelined mma.sync GEMM.
// C[M,Nc] = A[M,K] @ Wt[Nc,K]^T (+ cbias), A/W pre-split into hi/lo bf16.
// 128x128x32 CTA tile, 8 warps (2x4), warp tile 64x32, m16n8k16 HMMA.
// D += Ah*Bh + Ah*Bl + Al*Bh  (fp32 accum)
// 2-stage cp.async pipeline; no in-kernel conversion; no raw staging.
// Smem rows: 32 bf16 data padded to 40 (80B stride; 16B-aligned for cp.async,
// conflict-free for ldmatrix — verified in round 9).
// ---------------------------------------------------------------------------
static constexpr int TSZ  = 10240;      // one operand tile: 128 rows * 80B
static constexpr int STG  = 4 * TSZ;    // stage stride (Ah,Al,Bh,Bl)
static constexpr int SOFF_AH = 0;
static constexpr int SOFF_AL = TSZ;
static constexpr int SOFF_BH = 2 * TSZ;
static constexpr int SOFF_BL = 3 * TSZ;
static constexpr int SMEM_MMA = 2 * STG;   // 81920 B

template <bool C_BIAS>
__global__ __launch_bounds__(256, 2)
void gemm_bf16_kernel(const __nv_bfloat16* __restrict__ Ahg,
                      const __nv_bfloat16* __restrict__ Alg,
                      const __nv_bfloat16* __restrict__ Bhg,   // [n][k]
                      const __nv_bfloat16* __restrict__ Blg,
                      const float* __restrict__ cb,
                      float* __restrict__ C, int M, int K, int Nc) {
    extern __shared__ __align__(16) char smem[];
    const uint32_t sbase = (uint32_t)__cvta_generic_to_shared(smem);

    const int tid = threadIdx.x;
    const int lane = tid & 31;
    const int wid = tid >> 5;
    const int wr = wid >> 2;        // 0..1 (warp row)
    const int wc = wid & 3;         // 0..3 (warp col)
    const int rowBase = blockIdx.y * 128;
    const int colBase = blockIdx.x * 128;

    const int lrow = lane & 7;
    const int lgrp = lane >> 3;

    float acc[4][4][4];
#pragma unroll
    for (int i = 0; i < 4; ++i)
#pragma unroll
        for (int j = 0; j < 4; ++j)
#pragma unroll
            for (int k = 0; k < 4; ++k) acc[i][j][k] = 0.f;

    // cp.async one 32-wide K chunk of all four operand tiles into stage sbuf
    auto issue_loads = [&](int k0, int sbuf) {
        uint32_t base = sbase + sbuf * STG;
#pragma unroll
        for (int j = 0; j < 2; ++j) {
            int lin = tid + j * 256;        // 0..511 (128 rows x 4 chunks)
            int r = lin >> 2;
            int q = lin & 3;
            uint32_t doff = (uint32_t)(r * 80 + q * 16);
            int grow = rowBase + r;
            bool ok = grow < M;
            size_t aoff = (size_t)(ok ? grow : 0) * K + k0 + q * 8;
            cp16(base + SOFF_AH + doff, Ahg + aoff, ok);
            cp16(base + SOFF_AL + doff, Alg + aoff, ok);
            size_t boff = (size_t)(colBase + r) * K + k0 + q * 8;
            cp16(base + SOFF_BH + doff, Bhg + boff, true);
            cp16(base + SOFF_BL + doff, Blg + boff, true);
        }
        cp_commit();
    };

    const int nChunks = K >> 5;
    issue_loads(0, 0);
    for (int c = 0; c < nChunks; ++c) {
        if (c + 1 < nChunks) {
            issue_loads((c + 1) << 5, (c + 1) & 1);
            cp_wait1();
        } else {
            cp_wait0();
        }
        __syncthreads();

        const uint32_t base = sbase + (c & 1) * STG;
#pragma unroll
        for (int ks = 0; ks < 32; ks += 16) {
            uint32_t aH[4][4], aL[4][4], bH[4][2], bL[4][2];
#pragma unroll
            for (int mf = 0; mf < 4; ++mf) {
                int r = wr * 64 + mf * 16 + lrow + ((lgrp & 1) ? 8 : 0);
                int cc = ks + ((lgrp & 2) ? 8 : 0);
                uint32_t off = (uint32_t)(r * 40 + cc) * 2;
                ldsm4(aH[mf], base + SOFF_AH + off);
                ldsm4(aL[mf], base + SOFF_AL + off);
            }
#pragma unroll
            for (int nf2 = 0; nf2 < 2; ++nf2) {
                int r = wc * 32 + nf2 * 16 + lrow + ((lgrp >> 1) ? 8 : 0);
                int cc = ks + ((lgrp & 1) ? 8 : 0);
                uint32_t off = (uint32_t)(r * 40 + cc) * 2;
                uint32_t t[4];
                ldsm4(t, base + SOFF_BH + off);
                bH[nf2 * 2][0] = t[0]; bH[nf2 * 2][1] = t[1];
                bH[nf2 * 2 + 1][0] = t[2]; bH[nf2 * 2 + 1][1] = t[3];
                ldsm4(t, base + SOFF_BL + off);
                bL[nf2 * 2][0] = t[0]; bL[nf2 * 2][1] = t[1];
                bL[nf2 * 2 + 1][0] = t[2]; bL[nf2 * 2 + 1][1] = t[3];
            }
#pragma unroll
            for (int mf = 0; mf < 4; ++mf)
#pragma unroll
                for (int nf = 0; nf < 4; ++nf) {
                    mma_bf16(acc[mf][nf], aH[mf], bH[nf]);
                    mma_bf16(acc[mf][nf], aH[mf], bL[nf]);
                    mma_bf16(acc[mf][nf], aL[mf], bH[nf]);
                }
        }
        __syncthreads();   // all warps done with this stage before re-fill
    }

    // ---- epilogue ----
#pragma unroll
    for (int mf = 0; mf < 4; ++mf) {
        int row = rowBase + wr * 64 + mf * 16 + (lane >> 2);
#pragma unroll
        for (int nf = 0; nf < 4; ++nf) {
            int col = colBase + wc * 32 + nf * 8 + (lane & 3) * 2;
            float b0 = 0.f, b1 = 0.f;
            if (C_BIAS) { b0 = cb[col]; b1 = cb[col + 1]; }
            if (row < M)
                *(float2*)(C + (size_t)row * Nc + col) =
                    make_float2(acc[mf][nf][0] + b0, acc[mf][nf][1] + b1);
            if (row + 8 < M)
                *(float2*)(C + (size_t)(row + 8) * Nc + col) =
                    make_float2(acc[mf][nf][2] + b0, acc[mf][nf][3] + b1);
        }
    }
}

// ---------------------------------------------------------------------------
// CSR aggregation + fused bias(+ReLU) + bf16 hi/lo split epilogue.
// Oh/Ol[i,:] = split( epi( sn[i]*H[i,:] + sum_e wgt[e]*H[src[e],:] + bias ) )
// One warp per destination node; register accumulation; no atomics.
// ---------------------------------------------------------------------------
template <int D, bool RELU>
__global__ __launch_bounds__(256)
void agg_csr_split_kernel(const float* __restrict__ H,
                          const int* __restrict__ rowptr,
                          const int* __restrict__ src,
                          const float* __restrict__ wgt,
                          const float* __restrict__ sn,
                          const float* __restrict__ bias,
                          __nv_bfloat16* __restrict__ Oh,
                          __nv_bfloat16* __restrict__ Ol, int n) {
    constexpr int V = D / 128;
    int node = (blockIdx.x * 256 + threadIdx.x) >> 5;
    int lane = threadIdx.x & 31;
    if (node >= n) return;

    float s = __ldg(&sn[node]);
    const float4* hself = (const float4*)(H + (size_t)node * D);
    float4 acc[V];
#pragma unroll
    for (int v = 0; v < V; ++v) {
        float4 h = __ldg(&hself[lane + 32 * v]);
        acc[v] = make_float4(h.x * s, h.y * s, h.z * s, h.w * s);
    }

    int e0 = __ldg(&rowptr[node]);
    int e1 = __ldg(&rowptr[node + 1]);
    for (int e = e0; e < e1; ++e) {
        int r = __ldg(&src[e]);
        float nm = __ldg(&wgt[e]);
        const float4* hs = (const float4*)(H + (size_t)r * D);
#pragma unroll
        for (int v = 0; v < V; ++v) {
            float4 h = __ldg(&hs[lane + 32 * v]);
            acc[v].x += nm * h.x;
            acc[v].y += nm * h.y;
            acc[v].z += nm * h.z;
            acc[v].w += nm * h.w;
        }
    }

#pragma unroll
    for (int v = 0; v < V; ++v) {
        int feat = 4 * (lane + 32 * v);
        float4 bb = *(const float4*)(bias + feat);
        float f[4] = {acc[v].x + bb.x, acc[v].y + bb.y,
                      acc[v].z + bb.z, acc[v].w + bb.w};
        if (RELU) {
#pragma unroll
            for (int j = 0; j < 4; ++j) f[j] = fmaxf(f[j], 0.f);
        }
        __nv_bfloat16 h[4], l[4];
#pragma unroll
        for (int j = 0; j < 4; ++j) split2(f[j], h[j], l[j]);
        *(uint2*)(Oh + (size_t)node * D + feat) = *(const uint2*)h;
        *(uint2*)(Ol + (size_t)node * D + feat) = *(const uint2*)l;
    }
}

// ---------------------------------------------------------------------------
// Launcher. gemm1 stays at launch index 3 (profiled slot).
// ---------------------------------------------------------------------------
extern "C" void kernel_launch(void* const* d_in, const int* in_sizes, int n_in,
                              void* d_out, int out_size) {
    const float* x  = (const float*)d_in[0];
    const int*   ei = (const int*)d_in[1];     // int32 (JAX x64 disabled)
    const float* ew = (const float*)d_in[2];
    const float* W1 = (const float*)d_in[3];
    const float* b1 = (const float*)d_in[4];
    const float* W2 = (const float*)d_in[5];
    const float* b2 = (const float*)d_in[6];
    const float* Wp = (const float*)d_in[7];
    const float* bp = (const float*)d_in[8];
    float* out = (float*)d_out;

    const int M = in_sizes[0] / 512;   // 50000
    const int E = in_sizes[2];         // 800000

    float *deg, *dinv, *sn, *H1, *H2, *wgt;
    int *cnt, *rowptr, *fill, *src, *part;
    __nv_bfloat16 *Xh, *Xl, *A1h, *A1l, *A2h, *A2l;
    __nv_bfloat16 *W1h, *W1l, *W2h, *W2l, *Wph, *Wpl;
    cudaGetSymbolAddress((void**)&deg,    g_deg);
    cudaGetSymbolAddress((void**)&dinv,   g_dinv);
    cudaGetSymbolAddress((void**)&sn,     g_sn);
    cudaGetSymbolAddress((void**)&H1,     g_H1);
    cudaGetSymbolAddress((void**)&H2,     g_H2);
    cudaGetSymbolAddress((void**)&cnt,    g_cnt);
    cudaGetSymbolAddress((void**)&rowptr, g_rowptr);
    cudaGetSymbolAddress((void**)&fill,   g_fill);
    cudaGetSymbolAddress((void**)&src,    g_src);
    cudaGetSymbolAddress((void**)&wgt,    g_wgt);
    cudaGetSymbolAddress((void**)&part,   g_part);
    cudaGetSymbolAddress((void**)&Xh,  g_Xh);
    cudaGetSymbolAddress((void**)&Xl,  g_Xl);
    cudaGetSymbolAddress((void**)&A1h, g_A1h);
    cudaGetSymbolAddress((void**)&A1l, g_A1l);
    cudaGetSymbolAddress((void**)&A2h, g_A2h);
    cudaGetSymbolAddress((void**)&A2l, g_A2l);
    cudaGetSymbolAddress((void**)&W1h, g_W1h);
    cudaGetSymbolAddress((void**)&W1l, g_W1l);
    cudaGetSymbolAddress((void**)&W2h, g_W2h);
    cudaGetSymbolAddress((void**)&W2l, g_W2l);
    cudaGetSymbolAddress((void**)&Wph, g_Wph);
    cudaGetSymbolAddress((void**)&Wpl, g_Wpl);

    cudaFuncSetAttribute(gemm_bf16_kernel<false>,
                         cudaFuncAttributeMaxDynamicSharedMemorySize, SMEM_MMA);
    cudaFuncSetAttribute(gemm_bf16_kernel<true>,
                         cudaFuncAttributeMaxDynamicSharedMemorySize, SMEM_MMA);

    const int TB = 256;
    const int rowBlocks = (M + 127) / 128;     // 391
    const int aggBlocks = (M + 7) / 8;
    const int nblk = (M + SCAN_BLK - 1) / SCAN_BLK;
    const size_t x4 = (size_t)M * 512 / 4;

    // launches 0..2 (before profiled slot): operand prep + deg init
    split_x_kernel<<<(int)((x4 + 255) / 256), TB>>>(x, Xh, Xl, x4);
    split_wT_kernel<<<(512 * 256 + 255) / 256, TB>>>(W1, W1h, W1l, 512, 256);
    deg_init_kernel<<<(M + TB - 1) / TB, TB>>>(deg, cnt, M);

    // launch 3 (profiled): H1 = x @ W1  (pure-bf16 pipelined HMMA)
    gemm_bf16_kernel<false>
        <<<dim3(2, rowBlocks), 256, SMEM_MMA>>>(Xh, Xl, W1h, W1l, nullptr,
                                                H1, M, 512, 256);

    // remaining prep + CSR build
    split_wT_kernel<<<(256 * 128 + 255) / 256, TB>>>(W2, W2h, W2l, 256, 128);
    split_wT_kernel<<<(128 * 128 + 255) / 256, TB>>>(Wp, Wph, Wpl, 128, 128);
    deg_accum_kernel<<<(E + TB - 1) / TB, TB>>>(ei, ew, deg, cnt, E, M);
    dinv_kernel<<<(M + TB - 1) / TB, TB>>>(deg, dinv, sn, M);
    scan_reduce_kernel<<<nblk, 256>>>(cnt, part, M);
    scan_partials_kernel<<<1, 64>>>(part, nblk);
    scan_final_kernel<<<nblk, 1024>>>(cnt, part, rowptr, fill, M);
    scatter_kernel<<<(E + TB - 1) / TB, TB>>>(ei, ew, dinv, fill, src, wgt, E, M);

    // layer 1 aggregation + fused relu(·+b1) + split -> A1h/A1l
    agg_csr_split_kernel<256, true>
        <<<aggBlocks, 256>>>(H1, rowptr, src, wgt, sn, b1, A1h, A1l, M);

    // layer 2: H2 = relu(AG1+b1) @ W2
    gemm_bf16_kernel<false>
        <<<dim3(1, rowBlocks), 256, SMEM_MMA>>>(A1h, A1l, W2h, W2l, nullptr,
                                                H2, M, 256, 128);

    // layer 2 aggregation + fused (·+b2) + split -> A2h/A2l
    agg_csr_split_kernel<128, false>
        <<<aggBlocks, 256>>>(H2, rowptr, src, wgt, sn, b2, A2h, A2l, M);

    // projection: out = (AG2+b2) @ Wp + bp
    gemm_bf16_kernel<true>
        <<<dim3(1, rowBlocks), 256, SMEM_MMA>>>(A2h, A2l, Wph, Wpl, bp,
                                                out, M, 128, 128);
}

// round 12
// speedup vs baseline: 1.1185x; 1.0374x over previous
#include <cuda_runtime.h>
#include <cuda_bf16.h>
#include <cstdint>

// Problem constants (shapes fixed by the dataset)
static constexpr int NMAX = 50000;
static constexpr int EMAX = 800000;
static constexpr int SCAN_BLK = 1024;

// Scratch (static device allocations — no cudaMalloc allowed).
__device__ __align__(16) float g_deg[NMAX];                // self-restoring (0)
__device__ __align__(16) float g_dinv[NMAX];
__device__ __align__(16) float g_sn[NMAX];                 // dinv^2 (self-loop norm)
__device__ __align__(16) float g_H1[(size_t)NMAX * 256];   // x @ W1 (fp32)
__device__ __align__(16) float g_AG1[(size_t)NMAX * 256];  // aggregated layer1
__device__ __align__(16) float g_H2[(size_t)NMAX * 128];   // relu(AG1+b1) @ W2
__device__ __align__(16) float g_AG2[(size_t)NMAX * 128];  // aggregated layer2
__device__ __align__(16) int   g_cnt[NMAX];                // self-restoring (0)
__device__ __align__(16) int   g_rowptr[NMAX + 1];
__device__ __align__(16) int   g_fill[NMAX];
__device__ __align__(16) int   g_src[EMAX];
__device__ __align__(16) float g_wgt[EMAX];
__device__ __align__(16) int   g_part[64];
// pre-split bf16 weights, transposed [n][k]
__device__ __align__(16) __nv_bfloat16 g_W1h[256 * 512], g_W1l[256 * 512];
__device__ __align__(16) __nv_bfloat16 g_W2h[128 * 256], g_W2l[128 * 256];
__device__ __align__(16) __nv_bfloat16 g_Wph[128 * 128], g_Wpl[128 * 128];

// ---------------------------------------------------------------------------
// mma.sync + cp.async helpers (base PTX ISA, sm_80+ — safe on plain sm_103)
// ---------------------------------------------------------------------------
__device__ __forceinline__ void ldsm4(uint32_t* r, uint32_t addr) {
    asm volatile(
        "ldmatrix.sync.aligned.m8n8.x4.shared.b16 {%0,%1,%2,%3}, [%4];"
        : "=r"(r[0]), "=r"(r[1]), "=r"(r[2]), "=r"(r[3]) : "r"(addr));
}
__device__ __forceinline__ void mma_bf16(float* c, const uint32_t* a,
                                         const uint32_t* b) {
    asm volatile(
        "mma.sync.aligned.m16n8k16.row.col.f32.bf16.bf16.f32 "
        "{%0,%1,%2,%3}, {%4,%5,%6,%7}, {%8,%9}, {%0,%1,%2,%3};"
        : "+f"(c[0]), "+f"(c[1]), "+f"(c[2]), "+f"(c[3])
        : "r"(a[0]), "r"(a[1]), "r"(a[2]), "r"(a[3]), "r"(b[0]), "r"(b[1]));
}
__device__ __forceinline__ void cp16(uint32_t dst, const void* src) {
    asm volatile("cp.async.cg.shared.global [%0], [%1], 16;"
                 :: "r"(dst), "l"(src));
}
__device__ __forceinline__ void cp_commit() {
    asm volatile("cp.async.commit_group;");
}
__device__ __forceinline__ void cp_wait0() {
    asm volatile("cp.async.wait_group 0;");
}
// bf16 hi/lo split (Markidis): v = hi + lo + O(2^-17 |v|)
__device__ __forceinline__ void split2(float v, __nv_bfloat16& h,
                                       __nv_bfloat16& l) {
    h = __float2bfloat16(v);
    l = __float2bfloat16(v - __bfloat162float(h));
}

// ---------------------------------------------------------------------------
// Weight pre-split: W[K][Nc] -> Wt[n][k] hi/lo (tiny matrices)
// ---------------------------------------------------------------------------
__global__ __launch_bounds__(256)
void split_wT_kernel(const float* __restrict__ W, __nv_bfloat16* __restrict__ wh,
                     __nv_bfloat16* __restrict__ wl, int K, int Nc) {
    int idx = blockIdx.x * 256 + threadIdx.x;
    if (idx >= K * Nc) return;
    int k = idx / Nc, n = idx - k * Nc;
    __nv_bfloat16 h, l;
    split2(W[idx], h, l);
    wh[(size_t)n * K + k] = h;
    wl[(size_t)n * K + k] = l;
}

// ---------------------------------------------------------------------------
// Degree / histogram (edge_index is int32: JAX x64 disabled).
// deg/cnt start at 0 (zero-init or restored by later kernels each iteration).
// ---------------------------------------------------------------------------
__global__ void deg_accum_kernel(const int* __restrict__ ei,
                                 const float* __restrict__ w,
                                 float* __restrict__ deg, int* __restrict__ cnt,
                                 int E, int n) {
    int e = blockIdx.x * blockDim.x + threadIdx.x;
    if (e < E) {
        int c = ei[E + e];
        if ((unsigned)c < (unsigned)n) {
            atomicAdd(&deg[c], w[e]);
            atomicAdd(&cnt[c], 1);
        }
    }
}

// d = deg + 1 (self-loop weight); also RESET deg to 0 for next graph replay.
__global__ void dinv_kernel(float* __restrict__ deg,
                            float* __restrict__ dinv,
                            float* __restrict__ sn, int n) {
    int i = blockIdx.x * blockDim.x + threadIdx.x;
    if (i < n) {
        float d = deg[i] + 1.0f;     // always > 0
        float v = rsqrtf(d);
        dinv[i] = v;
        sn[i] = v * v;
        deg[i] = 0.f;
    }
}

// ---- Multi-block exclusive scan ----
__global__ __launch_bounds__(256)
void scan_reduce_kernel(const int* __restrict__ cnt, int* __restrict__ part,
                        int n) {
    __shared__ int sh[256];
    int base = blockIdx.x * SCAN_BLK;
    int t = threadIdx.x;
    int s = 0;
#pragma unroll
    for (int j = 0; j < 4; ++j) {
        int i = base + t + j * 256;
        if (i < n) s += cnt[i];
    }
    sh[t] = s;
    __syncthreads();
    for (int o = 128; o > 0; o >>= 1) {
        if (t < o) sh[t] += sh[t + o];
        __syncthreads();
    }
    if (t == 0) part[blockIdx.x] = sh[0];
}

__global__ __launch_bounds__(64)
void scan_partials_kernel(int* __restrict__ part, int nblk) {
    __shared__ int ws[2];
    int t = threadIdx.x, lane = t & 31, wid = t >> 5;
    int v = (t < nblk) ? part[t] : 0;
    int s = v;
#pragma unroll
    for (int o = 1; o < 32; o <<= 1) {
        int u = __shfl_up_sync(0xffffffffu, s, o);
        if (lane >= o) s += u;
    }
    if (lane == 31) ws[wid] = s;
    __syncthreads();
    int excl = s - v + (wid ? ws[0] : 0);
    if (t < nblk) part[t] = excl;
}

// Final scan; also RESETS cnt to 0 for the next graph replay.
__global__ __launch_bounds__(1024)
void scan_final_kernel(int* __restrict__ cnt, const int* __restrict__ part,
                       int* __restrict__ rowptr, int* __restrict__ fill, int n) {
    __shared__ int wsum[32];
    __shared__ int wpre[32];
    int t = threadIdx.x, lane = t & 31, wid = t >> 5;
    int i = blockIdx.x * SCAN_BLK + t;
    int v = (i < n) ? cnt[i] : 0;
    int s = v;
#pragma unroll
    for (int o = 1; o < 32; o <<= 1) {
        int u = __shfl_up_sync(0xffffffffu, s, o);
        if (lane >= o) s += u;
    }
    if (lane == 31) wsum[wid] = s;
    __syncthreads();
    if (wid == 0) {
        int ws = wsum[lane];
#pragma unroll
        for (int o = 1; o < 32; o <<= 1) {
            int u = __shfl_up_sync(0xffffffffu, ws, o);
            if (lane >= o) ws += u;
        }
        wpre[lane] = ws;
    }
    __syncthreads();
    int excl = part[blockIdx.x] + (wid ? wpre[wid - 1] : 0) + s - v;
    if (i < n) {
        rowptr[i] = excl;
        fill[i] = excl;
        cnt[i] = 0;                     // restore for next replay
        if (i == n - 1) rowptr[n] = excl + v;
    }
}

__global__ void scatter_kernel(const int* __restrict__ ei,
                               const float* __restrict__ w,
                               const float* __restrict__ dinv,
                               int* __restrict__ fill,
                               int* __restrict__ src, float* __restrict__ wgt,
                               int E, int n) {
    int e = blockIdx.x * blockDim.x + threadIdx.x;
    if (e < E) {
        int c = ei[E + e];
        if ((unsigned)c < (unsigned)n) {
            int r = ei[e];
            bool rok = (unsigned)r < (unsigned)n;
            float nm = rok ? dinv[r] * w[e] * dinv[c] : 0.f;
            int pos = atomicAdd(&fill[c], 1);
            src[pos] = rok ? r : 0;
            wgt[pos] = nm;
        }
    }
}

// ---------------------------------------------------------------------------
// Hybrid bf16-split pipelined mma.sync GEMM.
// C[M,Nc] = epiA(A[M,K]) @ Wt[Nc,K]^T (+ cbias)
//   A: raw fp32, LDG -> register double-buffer -> (bias/relu) -> hi/lo split
//      at STS time (off the MMA critical path).
//   B: pre-split bf16 hi/lo, cp.async double-buffer.
// 128x128x32 CTA tile, 8 warps (2x4), warp tile 64x32, m16n8k16 HMMA.
// D += Ah*Bh + Ah*Bl + Al*Bh  (fp32 accum; ~6e-6 rel)
// ONE __syncthreads per chunk: between syncs, MMA reads stage s while
// STS/cp.async write stage 1-s (disjoint).
// ---------------------------------------------------------------------------
static constexpr int TSZ  = 10240;      // one operand tile: 128 rows * 80B
static constexpr int STG  = 4 * TSZ;    // stage stride (Ah,Al,Bh,Bl)
static constexpr int SOFF_AH = 0;
static constexpr int SOFF_AL = TSZ;
static constexpr int SOFF_BH = 2 * TSZ;
static constexpr int SOFF_BL = 3 * TSZ;
static constexpr int SMEM_MMA = 2 * STG;   // 81920 B

template <bool A_BIAS, bool A_RELU, bool C_BIAS>
__global__ __launch_bounds__(256, 2)
void gemm_hyb_kernel(const float* __restrict__ A,
                     const __nv_bfloat16* __restrict__ Bhg,   // [n][k]
                     const __nv_bfloat16* __restrict__ Blg,
                     const float* __restrict__ ab,
                     const float* __restrict__ cb,
                     float* __restrict__ C, int M, int K, int Nc) {
    extern __shared__ __align__(16) char smem[];
    const uint32_t sbase = (uint32_t)__cvta_generic_to_shared(smem);

    const int tid = threadIdx.x;
    const int lane = tid & 31;
    const int wid = tid >> 5;
    const int wr = wid >> 2;        // 0..1 (warp row)
    const int wc = wid & 3;         // 0..3 (warp col)
    const int rowBase = blockIdx.y * 128;
    const int colBase = blockIdx.x * 128;

    const int lrow = lane & 7;
    const int lgrp = lane >> 3;

    float acc[4][4][4];
#pragma unroll
    for (int i = 0; i < 4; ++i)
#pragma unroll
        for (int j = 0; j < 4; ++j)
#pragma unroll
            for (int k = 0; k < 4; ++k) acc[i][j][k] = 0.f;

    float4 abuf[4];   // A register double-buffer: 128x32 fp32 / 256 thr

    auto ldgA = [&](int k0) {
#pragma unroll
        for (int j = 0; j < 4; ++j) {
            int lin = tid + j * 256;        // 1024 float4 slots
            int r = lin >> 3;
            int q = lin & 7;
            int grow = rowBase + r;
            float4 v = make_float4(0.f, 0.f, 0.f, 0.f);
            if (grow < M)
                v = *(const float4*)(A + (size_t)grow * K + k0 + q * 4);
            if (A_BIAS) {
                float4 bb = *(const float4*)(ab + k0 + q * 4);
                v.x += bb.x; v.y += bb.y; v.z += bb.z; v.w += bb.w;
            }
            if (A_RELU) {
                v.x = fmaxf(v.x, 0.f); v.y = fmaxf(v.y, 0.f);
                v.z = fmaxf(v.z, 0.f); v.w = fmaxf(v.w, 0.f);
            }
            abuf[j] = v;
        }
    };
    auto stsA = [&](int sbuf) {
        uint32_t base = sbase + sbuf * STG;
#pragma unroll
        for (int j = 0; j < 4; ++j) {
            int lin = tid + j * 256;
            int r = lin >> 3;
            int q = lin & 7;
            __nv_bfloat16 h[4], l[4];
            split2(abuf[j].x, h[0], l[0]); split2(abuf[j].y, h[1], l[1]);
            split2(abuf[j].z, h[2], l[2]); split2(abuf[j].w, h[3], l[3]);
            uint32_t doff = (uint32_t)(r * 80 + q * 8);
            asm volatile("st.shared.b64 [%0], %1;" ::
                "r"(base + SOFF_AH + doff), "l"(*(const unsigned long long*)h));
            asm volatile("st.shared.b64 [%0], %1;" ::
                "r"(base + SOFF_AL + doff), "l"(*(const unsigned long long*)l));
        }
    };
    auto cpB = [&](int k0, int sbuf) {
        uint32_t base = sbase + sbuf * STG;
#pragma unroll
        for (int j = 0; j < 2; ++j) {
            int lin = tid + j * 256;        // 512 slots = 128 rows x 4 chunks
            int r = lin >> 2;
            int q = lin & 3;
            uint32_t doff = (uint32_t)(r * 80 + q * 16);
            size_t boff = (size_t)(colBase + r) * K + k0 + q * 8;
            cp16(base + SOFF_BH + doff, Bhg + boff);
            cp16(base + SOFF_BL + doff, Blg + boff);
        }
        cp_commit();
    };

    const int nChunks = K >> 5;
    ldgA(0);
    cpB(0, 0);
    for (int c = 0; c < nChunks; ++c) {
        const int s = c & 1;
        stsA(s);            // A regs (chunk c) -> stage s as hi/lo
        cp_wait0();         // B chunk c arrived (only outstanding group)
        __syncthreads();
        if (c + 1 < nChunks) {
            ldgA((c + 1) << 5);        // latency hidden under MMA phase
            cpB((c + 1) << 5, 1 - s);  // writes stage 1-s (disjoint from reads)
        }

        const uint32_t base = sbase + s * STG;
#pragma unroll
        for (int ks = 0; ks < 32; ks += 16) {
            uint32_t aH[4][4], aL[4][4], bH[4][2], bL[4][2];
#pragma unroll
            for (int mf = 0; mf < 4; ++mf) {
                int r = wr * 64 + mf * 16 + lrow + ((lgrp & 1) ? 8 : 0);
                int cc = ks + ((lgrp & 2) ? 8 : 0);
                uint32_t off = (uint32_t)(r * 40 + cc) * 2;
                ldsm4(aH[mf], base + SOFF_AH + off);
                ldsm4(aL[mf], base + SOFF_AL + off);
            }
#pragma unroll
            for (int nf2 = 0; nf2 < 2; ++nf2) {
                int r = wc * 32 + nf2 * 16 + lrow + ((lgrp >> 1) ? 8 : 0);
                int cc = ks + ((lgrp & 1) ? 8 : 0);
                uint32_t off = (uint32_t)(r * 40 + cc) * 2;
                uint32_t t[4];
                ldsm4(t, base + SOFF_BH + off);
                bH[nf2 * 2][0] = t[0]; bH[nf2 * 2][1] = t[1];
                bH[nf2 * 2 + 1][0] = t[2]; bH[nf2 * 2 + 1][1] = t[3];
                ldsm4(t, base + SOFF_BL + off);
                bL[nf2 * 2][0] = t[0]; bL[nf2 * 2][1] = t[1];
                bL[nf2 * 2 + 1][0] = t[2]; bL[nf2 * 2 + 1][1] = t[3];
            }
#pragma unroll
            for (int mf = 0; mf < 4; ++mf)
#pragma unroll
                for (int nf = 0; nf < 4; ++nf) {
                    mma_bf16(acc[mf][nf], aH[mf], bH[nf]);
                    mma_bf16(acc[mf][nf], aH[mf], bL[nf]);
                    mma_bf16(acc[mf][nf], aL[mf], bH[nf]);
                }
        }
    }

    // ---- epilogue ----
#pragma unroll
    for (int mf = 0; mf < 4; ++mf) {
        int row = rowBase + wr * 64 + mf * 16 + (lane >> 2);
#pragma unroll
        for (int nf = 0; nf < 4; ++nf) {
            int col = colBase + wc * 32 + nf * 8 + (lane & 3) * 2;
            float b0 = 0.f, b1 = 0.f;
            if (C_BIAS) { b0 = cb[col]; b1 = cb[col + 1]; }
            if (row < M)
                *(float2*)(C + (size_t)row * Nc + col) =
                    make_float2(acc[mf][nf][0] + b0, acc[mf][nf][1] + b1);
            if (row + 8 < M)
                *(float2*)(C + (size_t)(row + 8) * Nc + col) =
                    make_float2(acc[mf][nf][2] + b0, acc[mf][nf][3] + b1);
        }
    }
}

// ---------------------------------------------------------------------------
// CSR aggregation: one warp per destination node (no atomics), fp32 out.
// ---------------------------------------------------------------------------
template <int D>
__global__ __launch_bounds__(256)
void agg_csr_kernel(const float* __restrict__ H,
                    const int* __restrict__ rowptr,
                    const int* __restrict__ src,
                    const float* __restrict__ wgt,
                    const float* __restrict__ sn,
                    float* __restrict__ AG, int n) {
    constexpr int V = D / 128;
    int node = (blockIdx.x * 256 + threadIdx.x) >> 5;
    int lane = threadIdx.x & 31;
    if (node >= n) return;

    float s = __ldg(&sn[node]);
    const float4* hself = (const float4*)(H + (size_t)node * D);
    float4 acc[V];
#pragma unroll
    for (int v = 0; v < V; ++v) {
        float4 h = __ldg(&hself[lane + 32 * v]);
        acc[v] = make_float4(h.x * s, h.y * s, h.z * s, h.w * s);
    }

    int e0 = __ldg(&rowptr[node]);
    int e1 = __ldg(&rowptr[node + 1]);
    for (int e = e0; e < e1; ++e) {
        int r = __ldg(&src[e]);
        float nm = __ldg(&wgt[e]);
        const float4* hs = (const float4*)(H + (size_t)r * D);
#pragma unroll
        for (int v = 0; v < V; ++v) {
            float4 h = __ldg(&hs[lane + 32 * v]);
            acc[v].x += nm * h.x;
            acc[v].y += nm * h.y;
            acc[v].z += nm * h.z;
            acc[v].w += nm * h.w;
        }
    }

    float4* dst = (float4*)(AG + (size_t)node * D);
#pragma unroll
    for (int v = 0; v < V; ++v) dst[lane + 32 * v] = acc[v];
}

// ---------------------------------------------------------------------------
// Launcher. gemm1 stays at launch index 3 (profiled slot).
// ---------------------------------------------------------------------------
extern "C" void kernel_launch(void* const* d_in, const int* in_sizes, int n_in,
                              void* d_out, int out_size) {
    const float* x  = (const float*)d_in[0];
    const int*   ei = (const int*)d_in[1];     // int32 (JAX x64 disabled)
    const float* ew = (const float*)d_in[2];
    const float* W1 = (const float*)d_in[3];
    const float* b1 = (const float*)d_in[4];
    const float* W2 = (const float*)d_in[5];
    const float* b2 = (const float*)d_in[6];
    const float* Wp = (const float*)d_in[7];
    const float* bp = (const float*)d_in[8];
    float* out = (float*)d_out;

    const int M = in_sizes[0] / 512;   // 50000
    const int E = in_sizes[2];         // 800000

    float *deg, *dinv, *sn, *H1, *AG1, *H2, *AG2, *wgt;
    int *cnt, *rowptr, *fill, *src, *part;
    __nv_bfloat16 *W1h, *W1l, *W2h, *W2l, *Wph, *Wpl;
    cudaGetSymbolAddress((void**)&deg,    g_deg);
    cudaGetSymbolAddress((void**)&dinv,   g_dinv);
    cudaGetSymbolAddress((void**)&sn,     g_sn);
    cudaGetSymbolAddress((void**)&H1,     g_H1);
    cudaGetSymbolAddress((void**)&AG1,    g_AG1);
    cudaGetSymbolAddress((void**)&H2,     g_H2);
    cudaGetSymbolAddress((void**)&AG2,    g_AG2);
    cudaGetSymbolAddress((void**)&cnt,    g_cnt);
    cudaGetSymbolAddress((void**)&rowptr, g_rowptr);
    cudaGetSymbolAddress((void**)&fill,   g_fill);
    cudaGetSymbolAddress((void**)&src,    g_src);
    cudaGetSymbolAddress((void**)&wgt,    g_wgt);
    cudaGetSymbolAddress((void**)&part,   g_part);
    cudaGetSymbolAddress((void**)&W1h, g_W1h);
    cudaGetSymbolAddress((void**)&W1l, g_W1l);
    cudaGetSymbolAddress((void**)&W2h, g_W2h);
    cudaGetSymbolAddress((void**)&W2l, g_W2l);
    cudaGetSymbolAddress((void**)&Wph, g_Wph);
    cudaGetSymbolAddress((void**)&Wpl, g_Wpl);

    cudaFuncSetAttribute(gemm_hyb_kernel<false, false, false>,
                         cudaFuncAttributeMaxDynamicSharedMemorySize, SMEM_MMA);
    cudaFuncSetAttribute(gemm_hyb_kernel<true, true, false>,
                         cudaFuncAttributeMaxDynamicSharedMemorySize, SMEM_MMA);
    cudaFuncSetAttribute(gemm_hyb_kernel<true, false, true>,
                         cudaFuncAttributeMaxDynamicSharedMemorySize, SMEM_MMA);

    const int TB = 256;
    const int rowBlocks = (M + 127) / 128;     // 391
    const int aggBlocks = (M + 7) / 8;
    const int nblk = (M + SCAN_BLK - 1) / SCAN_BLK;

    // launches 0..2
    split_wT_kernel<<<(512 * 256 + 255) / 256, TB>>>(W1, W1h, W1l, 512, 256);
    deg_accum_kernel<<<(E + TB - 1) / TB, TB>>>(ei, ew, deg, cnt, E, M);
    dinv_kernel<<<(M + TB - 1) / TB, TB>>>(deg, dinv, sn, M);

    // launch 3 (profiled): H1 = x @ W1
    gemm_hyb_kernel<false, false, false>
        <<<dim3(2, rowBlocks), 256, SMEM_MMA>>>(x, W1h, W1l, nullptr, nullptr,
                                                H1, M, 512, 256);

    // remaining weight splits + CSR build
    split_wT_kernel<<<(256 * 128 + 255) / 256, TB>>>(W2, W2h, W2l, 256, 128);
    split_wT_kernel<<<(128 * 128 + 255) / 256, TB>>>(Wp, Wph, Wpl, 128, 128);
    scan_reduce_kernel<<<nblk, 256>>>(cnt, part, M);
    scan_partials_kernel<<<1, 64>>>(part, nblk);
    scan_final_kernel<<<nblk, 1024>>>(cnt, part, rowptr, fill, M);
    scatter_kernel<<<(E + TB - 1) / TB, TB>>>(ei, ew, dinv, fill, src, wgt, E, M);

    // layer 1 aggregation (fp32)
    agg_csr_kernel<256><<<aggBlocks, 256>>>(H1, rowptr, src, wgt, sn, AG1, M);

    // layer 2: H2 = relu(AG1 + b1) @ W2  (bias+relu fused into A load)
    gemm_hyb_kernel<true, true, false>
        <<<dim3(1, rowBlocks), 256, SMEM_MMA>>>(AG1, W2h, W2l, b1, nullptr,
                                                H2, M, 256, 128);

    // layer 2 aggregation (fp32)
    agg_csr_kernel<128><<<aggBlocks, 256>>>(H2, rowptr, src, wgt, sn, AG2, M);

    // projection: out = (AG2 + b2) @ Wp + bp
    gemm_hyb_kernel<true, false, true>
        <<<dim3(1, rowBlocks), 256, SMEM_MMA>>>(AG2, Wph, Wpl, b2, bp,
                                                out, M, 128, 128);
}